// round 8
// baseline (speedup 1.0000x reference)
#include <cuda_runtime.h>

// Shape: [1, 8, 8, 8, 258, 258, 1] fp32; total = 34,080,768 elems = 8,520,192 float4.
//
// Pass 1 (fully branchless streaming): out = remap_w(x) * hm.
//   Since 66564 = 258^2, w0 = idx % 258 (single magic-mul mod, no h needed).
//   258 % 4 == 2 -> w-edge sources live in the same 16B chunk:
//     w0==0   : lane0 <- v.y   (x[h][1])
//     w0==254 : lane3 <- v.z   (x[h][256])
//     w0==256 : lane1 <- v.x   (x[h][256]),  lane2 <- v.w (x[h+1][1])
//   h-edge rows (h = 0, 257) are written with provisional values.
//
// Pass 2 (row fixup, ~3MB traffic): rewrites rows 0 and 257 of each image:
//     w==0 -> x[row][1], w==257 -> x[row][256] (w-rule, ORIGINAL h),
//     else row 0 -> x[1][w], row 257 -> x[256][w].
//   Rows are contiguous 1032B spans -> fully coalesced, unlike the R2 column
//   fixup that cost 12.5us.

#define HW        258
#define IMG_ELEMS 66564u
#define TOTAL4    8520192u     // float4 chunks; 33282 blocks * 256 exactly
#define NIMG      512u

__global__ __launch_bounds__(256)
void halo_main_kernel(const float* __restrict__ x,
                      const float4* __restrict__ hm,
                      float4* __restrict__ out)
{
    unsigned i = blockIdx.x * 256u + threadIdx.x;   // exact cover
    unsigned idx = i * 4u;

    float4 v = __ldcs(reinterpret_cast<const float4*>(x + idx));
    float4 b = __ldcs(hm + i);

    unsigned w0 = idx % (unsigned)HW;   // 0..256, even

    float a0 = (w0 == 0u)        ? v.y : v.x;
    float a1 = (w0 == HW - 2u)   ? v.x : v.y;
    float a2 = (w0 == HW - 2u)   ? v.w : v.z;
    float a3 = (w0 == HW - 4u)   ? v.z : v.w;

    float4 r;
    r.x = a0 * b.x;
    r.y = a1 * b.y;
    r.z = a2 * b.z;
    r.w = a3 * b.w;
    __stcs(out + i, r);
}

#define FIXN (NIMG * 2u * (unsigned)HW)   // 264,192 = 1032 blocks * 256 exactly

__global__ __launch_bounds__(256)
void halo_rowfix_kernel(const float* __restrict__ x,
                        const float* __restrict__ hm,
                        float* __restrict__ out)
{
    unsigned t = blockIdx.x * 256u + threadIdx.x;   // exact cover
    unsigned img = t / (2u * HW);
    unsigned r   = t - img * (2u * HW);
    unsigned row = (r < HW) ? 0u : (HW - 1u);
    unsigned w   = (r < HW) ? r  : r - HW;

    unsigned sh, sw;
    if (w == 0u)            { sh = row;                      sw = 1u;      }
    else if (w == HW - 1u)  { sh = row;                      sw = HW - 2u; }
    else                    { sh = (row == 0u) ? 1u : HW-2u; sw = w;       }

    unsigned base = img * IMG_ELEMS;
    unsigned di   = base + row * (unsigned)HW + w;
    out[di] = __ldg(x + base + sh * (unsigned)HW + sw) * __ldg(hm + di);
}

extern "C" void kernel_launch(void* const* d_in, const int* in_sizes, int n_in,
                              void* d_out, int out_size)
{
    const float* x  = (const float*)d_in[0];
    const float* hm = (const float*)d_in[1];
    float* out = (float*)d_out;

    halo_main_kernel<<<TOTAL4 / 256, 256>>>(x, (const float4*)hm, (float4*)out);
    halo_rowfix_kernel<<<FIXN / 256, 256>>>(x, hm, out);
}

// round 9
// speedup vs baseline: 1.0362x; 1.0362x over previous
#include <cuda_runtime.h>

// Shape: [1, 8, 8, 8, 258, 258, 1] fp32; 512 images of 258x258.
// total = 34,080,768 elems = 8,520,192 float4 chunks = 16641 chunks/image.
//
// Single kernel, block-specialized (uniform branch on blockIdx, zero warp
// divergence):
//   EDGE blocks (first 260): own the 130 chunks/image that touch rows 0/257
//     (chunks 0..64 and 16576..16640). Full per-lane scalar remap.
//   INTERIOR blocks (33022): own chunks 65..16575 (rows 1..256 only).
//     Pure branchless stream: 258 % 4 == 2 puts every w-edge source in the
//     same 16B chunk -> 4 predicated SELs on w0 = idx % 258:
//       w0==0: lane0<-v.y   w0==254: lane3<-v.z   w0==256: lane1<-v.x, lane2<-v.w
// Remap rules (reads from ORIGINAL x; w-assigns run last so w-edges keep h):
//   w==0 -> +1, w==257 -> -1, else h==0 -> +258, h==257 -> -258, else 0.

#define HW          258
#define IMG_ELEMS   66564u
#define CHUNKS_IMG  16641u
#define INT_FIRST   65u        // first interior chunk in image
#define INT_PER_IMG 16511u     // chunks 65..16575
#define EDGE_PER_IMG 130u
#define EDGE_BLOCKS 260u       // 512*130/256
#define INT_BLOCKS  33022u     // 512*16511/256
#define GRID        (EDGE_BLOCKS + INT_BLOCKS)   // 33282

__global__ __launch_bounds__(256)
void halo_block_spec_kernel(const float* __restrict__ x,
                            const float4* __restrict__ hm,
                            float4* __restrict__ out)
{
    unsigned b = blockIdx.x;

    if (b >= EDGE_BLOCKS) {
        // ---------------- interior fast path (branchless) ----------------
        unsigned t   = (b - EDGE_BLOCKS) * 256u + threadIdx.x;  // exact cover
        unsigned img = t / INT_PER_IMG;
        unsigned c   = t - img * INT_PER_IMG + INT_FIRST;
        unsigned chunk = img * CHUNKS_IMG + c;
        unsigned idx = chunk * 4u;

        float4 v  = __ldcs(reinterpret_cast<const float4*>(x) + chunk);
        float4 bm = __ldcs(hm + chunk);

        unsigned w0 = idx % (unsigned)HW;   // 0..256, even (rows 1..256 only)

        float a0 = (w0 == 0u)      ? v.y : v.x;
        float a1 = (w0 == HW - 2u) ? v.x : v.y;
        float a2 = (w0 == HW - 2u) ? v.w : v.z;
        float a3 = (w0 == HW - 4u) ? v.z : v.w;

        float4 r;
        r.x = a0 * bm.x;
        r.y = a1 * bm.y;
        r.z = a2 * bm.z;
        r.w = a3 * bm.w;
        __stcs(out + chunk, r);
    } else {
        // ---------------- edge path (rows 0 / 257, per-lane remap) -------
        unsigned t   = b * 256u + threadIdx.x;                  // exact cover
        unsigned img = t / EDGE_PER_IMG;
        unsigned c   = t - img * EDGE_PER_IMG;
        unsigned cc  = (c < 65u) ? c : (INT_PER_IMG + c);       // 16576 + (c-65)
        unsigned chunk = img * CHUNKS_IMG + cc;
        unsigned idx = chunk * 4u;

        float4 bm = __ldcs(hm + chunk);

        unsigned rem = idx % IMG_ELEMS;
        unsigned h   = rem / (unsigned)HW;
        unsigned w   = rem - h * (unsigned)HW;

        float lane[4];
#pragma unroll
        for (int k = 0; k < 4; ++k) {
            int delta = 0;
            if (w == 0u)           delta = 1;     // w-edge keeps original h
            else if (w == HW - 1u) delta = -1;
            else if (h == 0u)      delta = HW;    // h-edge
            else if (h == HW - 1u) delta = -HW;
            lane[k] = __ldg(x + (int)(idx + k) + delta);
            if (++w == HW) { w = 0u; ++h; }
        }

        float4 r;
        r.x = lane[0] * bm.x;
        r.y = lane[1] * bm.y;
        r.z = lane[2] * bm.z;
        r.w = lane[3] * bm.w;
        __stcs(out + chunk, r);
    }
}

extern "C" void kernel_launch(void* const* d_in, const int* in_sizes, int n_in,
                              void* d_out, int out_size)
{
    const float* x  = (const float*)d_in[0];
    const float* hm = (const float*)d_in[1];
    float* out = (float*)d_out;

    halo_block_spec_kernel<<<GRID, 256>>>(x, (const float4*)hm, (float4*)out);
}